// round 8
// baseline (speedup 1.0000x reference)
#include <cuda_runtime.h>
#include <cuda_fp16.h>
#include <cstdint>

// ---------------------------------------------------------------------------
// out[b,s,o] = sum_i x[b,s,i] * (nf4[codes][o,i] * scale[o]) + bias[o]
// M = 8192, N = 4096, K = 4096, fp32 in/out.
// Plain sm_103 target (no tcgen05) -> legacy HMMA m16n8k16 pipe.
// R8: split-wave LDSM/MMA schedule inside each ks (4-deep LDSM exposure
// instead of 8-deep; second LDSM group + cp.asyncs hide under MMA wave 1),
// wider prep kernel (32 B/thread).
// ---------------------------------------------------------------------------

static constexpr int M_TOTAL = 8192;
static constexpr int N_TOTAL = 4096;
static constexpr int K_TOTAL = 4096;

static constexpr int BM = 128;
static constexpr int BN = 128;
static constexpr int BK = 64;            // 64 halfs = 128 B/row (SW128)
static constexpr int STAGES = 3;
static constexpr int KITERS = K_TOTAL / BK;   // 64
static constexpr int TILES = (M_TOTAL / BM) * (N_TOTAL / BN);  // 2048
static constexpr int GRID = 296;              // 2 CTAs x 148 SMs

static constexpr int A_BYTES = BM * 128;                 // 16 KB
static constexpr int B_BYTES = BN * 128;                 // 16 KB
static constexpr int STAGE_BYTES = A_BYTES + B_BYTES;    // 32 KB
static constexpr int SM_STAGE0 = 1024;
static constexpr int SMEM_BYTES = SM_STAGE0 + STAGES * STAGE_BYTES;  // 99328

__device__ __align__(1024) __half g_Wh[(size_t)N_TOTAL * K_TOTAL];  // 32 MB
__device__ __align__(1024) __half g_Xh[(size_t)M_TOTAL * K_TOTAL];  // 64 MB

__constant__ float c_nf4[16] = {
    -1.0f, -0.6961928f, -0.52507305f, -0.3949175f, -0.28444138f, -0.18477343f,
    -0.09105004f, 0.0f, 0.0795803f, 0.1609302f, 0.2461123f, 0.33791524f,
    0.44070983f, 0.562617f, 0.72295684f, 1.0f};

// ------------------------------- helpers -----------------------------------

__device__ __forceinline__ uint32_t smem_u32(const void* p) {
  uint32_t a;
  asm("{ .reg .u64 t; cvta.to.shared.u64 t, %1; cvt.u32.u64 %0, t; }"
      : "=r"(a) : "l"(p));
  return a;
}

#define SWZ128(b) ((b) ^ (((b) >> 3) & 0x70))

#define CP_ASYNC16(dst, gsrc)                                          \
  asm volatile("cp.async.cg.shared.global [%0], [%1], 16;" ::"r"(dst), \
               "l"(gsrc)                                               \
               : "memory")

#define CP_ASYNC_MBAR_ARRIVE(mbar)                                           \
  asm volatile("cp.async.mbarrier.arrive.noinc.shared::cta.b64 [%0];" ::"r"( \
                   (uint32_t)(mbar))                                         \
               : "memory")

#define MBARRIER_INIT(addr, cnt)                                             \
  asm volatile("mbarrier.init.shared.b64 [%0], %1;" ::"r"((uint32_t)(addr)), \
               "r"((uint32_t)(cnt))                                          \
               : "memory")

#define MBARRIER_ARRIVE(addr)                               \
  asm volatile("mbarrier.arrive.shared.b64 _, [%0];" ::"r"( \
                   (uint32_t)(addr))                        \
               : "memory")

#define MBARRIER_WAIT_PARITY(mbar_smem_addr, phase_parity)                     \
  do {                                                                         \
    uint32_t _mbar = (uint32_t)(mbar_smem_addr);                               \
    uint32_t _parity = (uint32_t)(phase_parity);                               \
    uint32_t _done;                                                            \
    asm volatile(                                                              \
        "{\n\t.reg .pred p;\n\t"                                               \
        "mbarrier.try_wait.parity.acquire.cta.shared::cta.b64 p, [%1], %2;\n\t" \
        "selp.b32 %0, 1, 0, p;\n\t}"                                           \
        : "=r"(_done)                                                          \
        : "r"(_mbar), "r"(_parity)                                             \
        : "memory");                                                           \
    if (!_done) {                                                              \
      asm volatile(                                                            \
          "{\n\t.reg .pred P1;\n\t"                                            \
          "WAIT_LOOP_%=:\n\t"                                                  \
          "mbarrier.try_wait.parity.acquire.cta.shared::cta.b64 P1, [%0], %1, 0x989680;\n\t" \
          "@P1 bra.uni WAIT_DONE_%=;\n\t"                                      \
          "bra.uni WAIT_LOOP_%=;\n\t"                                          \
          "WAIT_DONE_%=:\n\t}" ::"r"(_mbar),                                   \
          "r"(_parity)                                                         \
          : "memory");                                                         \
    }                                                                          \
  } while (0)

#define MBARRIER_WAIT_PARITY_RELAXED(mbar_smem_addr, phase_parity)             \
  do {                                                                         \
    uint32_t _mbar = (uint32_t)(mbar_smem_addr);                               \
    uint32_t _parity = (uint32_t)(phase_parity);                               \
    uint32_t _done;                                                            \
    asm volatile(                                                              \
        "{\n\t.reg .pred p;\n\t"                                               \
        "mbarrier.try_wait.parity.relaxed.cta.shared::cta.b64 p, [%1], %2;\n\t" \
        "selp.b32 %0, 1, 0, p;\n\t}"                                           \
        : "=r"(_done)                                                          \
        : "r"(_mbar), "r"(_parity)                                             \
        : "memory");                                                           \
    if (!_done) {                                                              \
      asm volatile(                                                            \
          "{\n\t.reg .pred P1;\n\t"                                            \
          "WAIT_LOOP_%=:\n\t"                                                  \
          "mbarrier.try_wait.parity.relaxed.cta.shared::cta.b64 P1, [%0], %1, 0x989680;\n\t" \
          "@P1 bra.uni WAIT_DONE_%=;\n\t"                                      \
          "bra.uni WAIT_LOOP_%=;\n\t"                                          \
          "WAIT_DONE_%=:\n\t}" ::"r"(_mbar),                                   \
          "r"(_parity)                                                         \
          : "memory");                                                         \
    }                                                                          \
  } while (0)

#define LDSM_X4(r0, r1, r2, r3, addr)                                 \
  asm volatile(                                                       \
      "ldmatrix.sync.aligned.m8n8.x4.shared.b16 {%0,%1,%2,%3}, [%4];" \
      : "=r"(r0), "=r"(r1), "=r"(r2), "=r"(r3)                        \
      : "r"(addr))

#define MMA16816(c0, c1, c2, c3, a0, a1, a2, a3, b0, b1)              \
  asm volatile(                                                       \
      "mma.sync.aligned.m16n8k16.row.col.f32.f16.f16.f32 "            \
      "{%0,%1,%2,%3}, {%4,%5,%6,%7}, {%8,%9}, {%0,%1,%2,%3};"         \
      : "+f"(c0), "+f"(c1), "+f"(c2), "+f"(c3)                        \
      : "r"(a0), "r"(a1), "r"(a2), "r"(a3), "r"(b0), "r"(b1))

// ---------------------------- fused pre-kernel ------------------------------
// dequant: 8 int32 (32 nibbles -> 16 fp16 = 32 B) per thread.
// convert: 16 fp32 -> 16 fp16 (32 B) per thread.

static constexpr int DQ_BLOCKS = (N_TOTAL * K_TOTAL / 16) / 256;  // 4096
static constexpr int CV_BLOCKS = (M_TOTAL * K_TOTAL / 16) / 256;  // 8192

__global__ void k_prep(const int4* __restrict__ codes,
                       const float* __restrict__ scale,
                       const float4* __restrict__ x4) {
  if (blockIdx.x < DQ_BLOCKS) {
    __shared__ float cb[16];
    if (threadIdx.x < 16) cb[threadIdx.x] = c_nf4[threadIdx.x];
    __syncthreads();
    int t = blockIdx.x * 256 + threadIdx.x;  // 0 .. 1048575
    float s = scale[t >> 8];  // 2048 packed ints per out-row, 8 per thread
#pragma unroll
    for (int half = 0; half < 2; ++half) {
      int4 e = codes[2 * t + half];
      uint4 o;
      __half2 h;
      h = __floats2half2_rn(cb[e.x & 15] * s, cb[(e.x >> 4) & 15] * s);
      o.x = reinterpret_cast<uint32_t&>(h);
      h = __floats2half2_rn(cb[e.y & 15] * s, cb[(e.y >> 4) & 15] * s);
      o.y = reinterpret_cast<uint32_t&>(h);
      h = __floats2half2_rn(cb[e.z & 15] * s, cb[(e.z >> 4) & 15] * s);
      o.z = reinterpret_cast<uint32_t&>(h);
      h = __floats2half2_rn(cb[e.w & 15] * s, cb[(e.w >> 4) & 15] * s);
      o.w = reinterpret_cast<uint32_t&>(h);
      reinterpret_cast<uint4*>(g_Wh)[2 * t + half] = o;
    }
  } else {
    int t = (blockIdx.x - DQ_BLOCKS) * 256 + threadIdx.x;  // 0 .. 2097151
#pragma unroll
    for (int half = 0; half < 2; ++half) {
      float4 v0 = x4[4 * t + 2 * half];
      float4 v1 = x4[4 * t + 2 * half + 1];
      uint4 u;
      __half2 h;
      h = __floats2half2_rn(v0.x, v0.y);
      u.x = reinterpret_cast<uint32_t&>(h);
      h = __floats2half2_rn(v0.z, v0.w);
      u.y = reinterpret_cast<uint32_t&>(h);
      h = __floats2half2_rn(v1.x, v1.y);
      u.z = reinterpret_cast<uint32_t&>(h);
      h = __floats2half2_rn(v1.z, v1.w);
      u.w = reinterpret_cast<uint32_t&>(h);
      reinterpret_cast<uint4*>(g_Xh)[2 * t + half] = u;
    }
  }
}

// ------------------------------- GEMM kernel -------------------------------
// Persistent: 296 CTAs x 128 threads (4 warps, 64x64 warp tiles, 2 CTAs/SM).
// ks body: LDSM{a01,b01} -> 8 MMA -> LDSM{a23,b23}+cp.async -> 24 MMA.

__global__ __launch_bounds__(128, 2) void k_gemm(const float* __restrict__ bias,
                                                 float* __restrict__ out) {
  extern __shared__ char smem[];
  const uint32_t sb = smem_u32(smem);
  const int tid = threadIdx.x;
  const int wid = tid >> 5;
  const int lid = tid & 31;
  const int wm = wid & 1;
  const int wn = wid >> 1;

  if (tid == 0) {
#pragma unroll
    for (int s = 0; s < STAGES; ++s) {
      MBARRIER_INIT(sb + 8 * s, 128);       // full[s]
      MBARRIER_INIT(sb + 24 + 8 * s, 128);  // empty[s]
    }
  }
  __syncthreads();

  const int bid = blockIdx.x;
  const int ntiles = (TILES - bid + GRID - 1) / GRID;

  float c[4][8][4];
#pragma unroll
  for (int i = 0; i < 4; ++i)
#pragma unroll
    for (int j = 0; j < 8; ++j)
#pragma unroll
      for (int v = 0; v < 4; ++v) c[i][j][v] = 0.f;

  const int f_row = tid >> 3;  // 0..15
  const int f_u = tid & 7;
  const uint32_t f_sw_base = (uint32_t)(f_row * 128 + f_u * 16);

  auto tile_bases = [&](int t, const __half*& pa, const __half*& pb) {
    const int m0 = (t >> 5) * BM;
    const int n0 = (t & 31) * BN;
    pa = g_Xh + ((size_t)(m0 + f_row) * K_TOTAL + f_u * 8);
    pb = g_Wh + ((size_t)(n0 + f_row) * K_TOTAL + f_u * 8);
  };

  const __half *aCur, *bCur, *aNxt, *bNxt;
  tile_bases(bid, aCur, bCur);
  if (ntiles > 1) tile_bases(bid + GRID, aNxt, bNxt);
  else { aNxt = aCur; bNxt = bCur; }

  auto fill_part = [&](int s, const __half* pa, const __half* pb, int ktp,
                       int part) {
    const uint32_t stage = sb + SM_STAGE0 + s * STAGE_BYTES;
    const size_t kOff = (size_t)ktp * BK;
#pragma unroll
    for (int j = 0; j < 2; ++j) {
      const int i = part * 2 + j;  // 0..7
      CP_ASYNC16(stage + SWZ128(f_sw_base + (uint32_t)(i * 16 * 128)),
                 (const void*)(pa + kOff + (size_t)16 * i * K_TOTAL));
    }
#pragma unroll
    for (int j = 0; j < 2; ++j) {
      const int i = part * 2 + j;
      CP_ASYNC16(stage + A_BYTES +
                     SWZ128(f_sw_base + (uint32_t)(i * 16 * 128)),
                 (const void*)(pb + kOff + (size_t)16 * i * K_TOTAL));
    }
  };

  // prologue: fill stages 0,1 (tile 0, kt 0,1)
#pragma unroll
  for (int p = 0; p < 4; ++p) fill_part(0, aCur, bCur, 0, p);
  CP_ASYNC_MBAR_ARRIVE(sb + 8 * 0);
#pragma unroll
  for (int p = 0; p < 4; ++p) fill_part(1, aCur, bCur, 1, p);
  CP_ASYNC_MBAR_ARRIVE(sb + 8 * 1);

  const int a_row = wm * 64 + (lid & 15);
  const int a_kb = (lid >> 4) * 16;
  const int b_row = wn * 64 + ((lid >> 4) * 8) + (lid & 7);
  const int b_kb = ((lid >> 3) & 1) * 16;

  int sp = 2, pp = 1;    // produce stage/parity
  int sc = 0, cpar = 0;  // consume stage/parity

  for (int j = 0; j < ntiles; ++j) {
    const bool last_tile = (j == ntiles - 1);
    for (int kt = 0; kt < KITERS; ++kt) {
      const bool same_tile = (kt < KITERS - 2);
      const bool produce = same_tile || !last_tile;
      const __half* pa = same_tile ? aCur : aNxt;
      const __half* pb = same_tile ? bCur : bNxt;
      const int ktp = same_tile ? kt + 2 : kt - (KITERS - 2);

      MBARRIER_WAIT_PARITY(sb + 8 * sc, cpar);
      const uint32_t aBase = sb + SM_STAGE0 + sc * STAGE_BYTES;
      const uint32_t bBase = aBase + A_BYTES;
#pragma unroll
      for (int ks = 0; ks < 4; ++ks) {
        uint32_t a[4][4], b[4][4];
        // ---- wave 0: first half of frags ----
#pragma unroll
        for (int mt = 0; mt < 2; ++mt) {
          uint32_t off = (uint32_t)((a_row + mt * 16) * 128 + ks * 32 + a_kb);
          LDSM_X4(a[mt][0], a[mt][1], a[mt][2], a[mt][3], aBase + SWZ128(off));
        }
#pragma unroll
        for (int p = 0; p < 2; ++p) {
          uint32_t off = (uint32_t)((b_row + p * 16) * 128 + ks * 32 + b_kb);
          LDSM_X4(b[p][0], b[p][1], b[p][2], b[p][3], bBase + SWZ128(off));
        }
        // ---- MMA wave 1: mt 0,1 x nt 0..3 (uses a0,a1,b0,b1 only) ----
#pragma unroll
        for (int mt = 0; mt < 2; ++mt)
#pragma unroll
          for (int nt = 0; nt < 4; ++nt)
            MMA16816(c[mt][nt][0], c[mt][nt][1], c[mt][nt][2], c[mt][nt][3],
                     a[mt][0], a[mt][1], a[mt][2], a[mt][3],
                     b[nt >> 1][(nt & 1) * 2], b[nt >> 1][(nt & 1) * 2 + 1]);
        // ---- wave 0b: second half of frags (hidden under MMA wave 1) ----
#pragma unroll
        for (int mt = 2; mt < 4; ++mt) {
          uint32_t off = (uint32_t)((a_row + mt * 16) * 128 + ks * 32 + a_kb);
          LDSM_X4(a[mt][0], a[mt][1], a[mt][2], a[mt][3], aBase + SWZ128(off));
        }
#pragma unroll
        for (int p = 2; p < 4; ++p) {
          uint32_t off = (uint32_t)((b_row + p * 16) * 128 + ks * 32 + b_kb);
          LDSM_X4(b[p][0], b[p][1], b[p][2], b[p][3], bBase + SWZ128(off));
        }
        // ---- producer work sits in the MMA shadow ----
        if (produce) {
          if (ks == 0) MBARRIER_WAIT_PARITY_RELAXED(sb + 24 + 8 * sp, pp);
          fill_part(sp, pa, pb, ktp, ks);
        }
        if (ks == 3) {
          MBARRIER_ARRIVE(sb + 24 + 8 * sc);
          if (produce) CP_ASYNC_MBAR_ARRIVE(sb + 8 * sp);
        }
        // ---- MMA wave 2: mt 0,1 x nt 4..7 ----
#pragma unroll
        for (int mt = 0; mt < 2; ++mt)
#pragma unroll
          for (int nt = 4; nt < 8; ++nt)
            MMA16816(c[mt][nt][0], c[mt][nt][1], c[mt][nt][2], c[mt][nt][3],
                     a[mt][0], a[mt][1], a[mt][2], a[mt][3],
                     b[nt >> 1][(nt & 1) * 2], b[nt >> 1][(nt & 1) * 2 + 1]);
        // ---- MMA wave 3: mt 2,3 x nt 0..7 ----
#pragma unroll
        for (int mt = 2; mt < 4; ++mt)
#pragma unroll
          for (int nt = 0; nt < 8; ++nt)
            MMA16816(c[mt][nt][0], c[mt][nt][1], c[mt][nt][2], c[mt][nt][3],
                     a[mt][0], a[mt][1], a[mt][2], a[mt][3],
                     b[nt >> 1][(nt & 1) * 2], b[nt >> 1][(nt & 1) * 2 + 1]);
      }
      sp = (sp == 2) ? 0 : sp + 1;
      if (sp == 0) pp ^= 1;
      sc = (sc == 2) ? 0 : sc + 1;
      if (sc == 0) cpar ^= 1;
    }

    // ---- epilogue for tile j (next tile's fills already in flight) ----
    {
      const int t = bid + j * GRID;
      const int m0 = (t >> 5) * BM;
      const int n0 = (t & 31) * BN;
      const int mrow = m0 + wm * 64 + (lid >> 2);
      const int ncol = n0 + wn * 64 + (lid & 3) * 2;
#pragma unroll
      for (int mt = 0; mt < 4; ++mt) {
#pragma unroll
        for (int nt = 0; nt < 8; ++nt) {
          const float2 b2 =
              *reinterpret_cast<const float2*>(bias + ncol + nt * 8);
          float* p0 = out + (size_t)(mrow + mt * 16) * N_TOTAL + ncol + nt * 8;
          float* p1 = p0 + 8 * N_TOTAL;
          float2 v0 = {c[mt][nt][0] + b2.x, c[mt][nt][1] + b2.y};
          float2 v1 = {c[mt][nt][2] + b2.x, c[mt][nt][3] + b2.y};
          *reinterpret_cast<float2*>(p0) = v0;
          *reinterpret_cast<float2*>(p1) = v1;
          c[mt][nt][0] = 0.f;
          c[mt][nt][1] = 0.f;
          c[mt][nt][2] = 0.f;
          c[mt][nt][3] = 0.f;
        }
      }
    }

    aCur = aNxt;
    bCur = bNxt;
    if (j + 2 < ntiles) tile_bases(bid + (j + 2) * GRID, aNxt, bNxt);
  }
}

// ------------------------------- launcher ----------------------------------

extern "C" void kernel_launch(void* const* d_in, const int* in_sizes, int n_in,
                              void* d_out, int out_size) {
  const float* x = (const float*)d_in[0];
  const int* codes = (const int*)d_in[1];
  const float* scale = (const float*)d_in[2];
  const float* bias = (const float*)d_in[3];
  float* out = (float*)d_out;

  k_prep<<<DQ_BLOCKS + CV_BLOCKS, 256>>>((const int4*)codes, scale,
                                         (const float4*)x);

  cudaFuncSetAttribute(k_gemm, cudaFuncAttributeMaxDynamicSharedMemorySize,
                       SMEM_BYTES);
  k_gemm<<<GRID, 128, SMEM_BYTES>>>(bias, out);
}

// round 9
// speedup vs baseline: 1.0180x; 1.0180x over previous
#include <cuda_runtime.h>
#include <cuda_fp16.h>
#include <cstdint>

// ---------------------------------------------------------------------------
// out[b,s,o] = sum_i x[b,s,i] * (nf4[codes][o,i] * scale[o]) + bias[o]
// M = 8192, N = 4096, K = 4096, fp32 in/out.
// Plain sm_103 target (no tcgen05) -> legacy HMMA m16n8k16 pipe.
// R9: de-rendezvous the stage ring: early release at ks3 (all LDSM first),
// producer empty-wait deferred to ks1, and probe-ahead of the consumer
// full-wait so its fast-path latency hides under MMAs.
// ---------------------------------------------------------------------------

static constexpr int M_TOTAL = 8192;
static constexpr int N_TOTAL = 4096;
static constexpr int K_TOTAL = 4096;

static constexpr int BM = 128;
static constexpr int BN = 128;
static constexpr int BK = 64;            // 64 halfs = 128 B/row (SW128)
static constexpr int STAGES = 3;
static constexpr int KITERS = K_TOTAL / BK;  // 64

static constexpr int A_BYTES = BM * 128;                 // 16 KB
static constexpr int B_BYTES = BN * 128;                 // 16 KB
static constexpr int STAGE_BYTES = A_BYTES + B_BYTES;    // 32 KB
static constexpr int SM_STAGE0 = 1024;
static constexpr int SMEM_BYTES = SM_STAGE0 + STAGES * STAGE_BYTES;  // 99328

__device__ __align__(1024) __half g_Wh[(size_t)N_TOTAL * K_TOTAL];  // 32 MB
__device__ __align__(1024) __half g_Xh[(size_t)M_TOTAL * K_TOTAL];  // 64 MB

__constant__ float c_nf4[16] = {
    -1.0f, -0.6961928f, -0.52507305f, -0.3949175f, -0.28444138f, -0.18477343f,
    -0.09105004f, 0.0f, 0.0795803f, 0.1609302f, 0.2461123f, 0.33791524f,
    0.44070983f, 0.562617f, 0.72295684f, 1.0f};

// ------------------------------- helpers -----------------------------------

__device__ __forceinline__ uint32_t smem_u32(const void* p) {
  uint32_t a;
  asm("{ .reg .u64 t; cvta.to.shared.u64 t, %1; cvt.u32.u64 %0, t; }"
      : "=r"(a) : "l"(p));
  return a;
}

#define SWZ128(b) ((b) ^ (((b) >> 3) & 0x70))

#define CP_ASYNC16(dst, gsrc)                                          \
  asm volatile("cp.async.cg.shared.global [%0], [%1], 16;" ::"r"(dst), \
               "l"(gsrc)                                               \
               : "memory")

#define CP_ASYNC_MBAR_ARRIVE(mbar)                                           \
  asm volatile("cp.async.mbarrier.arrive.noinc.shared::cta.b64 [%0];" ::"r"( \
                   (uint32_t)(mbar))                                         \
               : "memory")

#define MBARRIER_INIT(addr, cnt)                                             \
  asm volatile("mbarrier.init.shared.b64 [%0], %1;" ::"r"((uint32_t)(addr)), \
               "r"((uint32_t)(cnt))                                          \
               : "memory")

#define MBARRIER_ARRIVE(addr)                               \
  asm volatile("mbarrier.arrive.shared.b64 _, [%0];" ::"r"( \
                   (uint32_t)(addr))                        \
               : "memory")

// Non-blocking single probe (acquire). res=1 if phase already complete.
#define MBARRIER_PROBE(res, mbar_smem_addr, phase_parity)                      \
  asm volatile(                                                                \
      "{\n\t.reg .pred p;\n\t"                                                 \
      "mbarrier.test_wait.parity.acquire.cta.shared::cta.b64 p, [%1], %2;\n\t" \
      "selp.b32 %0, 1, 0, p;\n\t}"                                             \
      : "=r"(res)                                                              \
      : "r"((uint32_t)(mbar_smem_addr)), "r"((uint32_t)(phase_parity))         \
      : "memory")

#define MBARRIER_WAIT_PARITY(mbar_smem_addr, phase_parity)                     \
  do {                                                                         \
    uint32_t _mbar = (uint32_t)(mbar_smem_addr);                               \
    uint32_t _parity = (uint32_t)(phase_parity);                               \
    uint32_t _done;                                                            \
    asm volatile(                                                              \
        "{\n\t.reg .pred p;\n\t"                                               \
        "mbarrier.try_wait.parity.acquire.cta.shared::cta.b64 p, [%1], %2;\n\t" \
        "selp.b32 %0, 1, 0, p;\n\t}"                                           \
        : "=r"(_done)                                                          \
        : "r"(_mbar), "r"(_parity)                                             \
        : "memory");                                                           \
    if (!_done) {                                                              \
      asm volatile(                                                            \
          "{\n\t.reg .pred P1;\n\t"                                            \
          "WAIT_LOOP_%=:\n\t"                                                  \
          "mbarrier.try_wait.parity.acquire.cta.shared::cta.b64 P1, [%0], %1, 0x989680;\n\t" \
          "@P1 bra.uni WAIT_DONE_%=;\n\t"                                      \
          "bra.uni WAIT_LOOP_%=;\n\t"                                          \
          "WAIT_DONE_%=:\n\t}" ::"r"(_mbar),                                   \
          "r"(_parity)                                                         \
          : "memory");                                                         \
    }                                                                          \
  } while (0)

#define MBARRIER_WAIT_PARITY_RELAXED(mbar_smem_addr, phase_parity)             \
  do {                                                                         \
    uint32_t _mbar = (uint32_t)(mbar_smem_addr);                               \
    uint32_t _parity = (uint32_t)(phase_parity);                               \
    uint32_t _done;                                                            \
    asm volatile(                                                              \
        "{\n\t.reg .pred p;\n\t"                                               \
        "mbarrier.try_wait.parity.relaxed.cta.shared::cta.b64 p, [%1], %2;\n\t" \
        "selp.b32 %0, 1, 0, p;\n\t}"                                           \
        : "=r"(_done)                                                          \
        : "r"(_mbar), "r"(_parity)                                             \
        : "memory");                                                           \
    if (!_done) {                                                              \
      asm volatile(                                                            \
          "{\n\t.reg .pred P1;\n\t"                                            \
          "WAIT_LOOP_%=:\n\t"                                                  \
          "mbarrier.try_wait.parity.relaxed.cta.shared::cta.b64 P1, [%0], %1, 0x989680;\n\t" \
          "@P1 bra.uni WAIT_DONE_%=;\n\t"                                      \
          "bra.uni WAIT_LOOP_%=;\n\t"                                          \
          "WAIT_DONE_%=:\n\t}" ::"r"(_mbar),                                   \
          "r"(_parity)                                                         \
          : "memory");                                                         \
    }                                                                          \
  } while (0)

#define LDSM_X4(r0, r1, r2, r3, addr)                                 \
  asm volatile(                                                       \
      "ldmatrix.sync.aligned.m8n8.x4.shared.b16 {%0,%1,%2,%3}, [%4];" \
      : "=r"(r0), "=r"(r1), "=r"(r2), "=r"(r3)                        \
      : "r"(addr))

#define MMA16816(c0, c1, c2, c3, a0, a1, a2, a3, b0, b1)              \
  asm volatile(                                                       \
      "mma.sync.aligned.m16n8k16.row.col.f32.f16.f16.f32 "            \
      "{%0,%1,%2,%3}, {%4,%5,%6,%7}, {%8,%9}, {%0,%1,%2,%3};"         \
      : "+f"(c0), "+f"(c1), "+f"(c2), "+f"(c3)                        \
      : "r"(a0), "r"(a1), "r"(a2), "r"(a3), "r"(b0), "r"(b1))

// ---------------------------- fused pre-kernel ------------------------------

static constexpr int DQ_BLOCKS = (N_TOTAL * K_TOTAL / 8) / 256;  // 8192
static constexpr int CV_BLOCKS = (M_TOTAL * K_TOTAL / 8) / 256;  // 16384

__global__ void k_prep(const int4* __restrict__ codes,
                       const float* __restrict__ scale,
                       const float4* __restrict__ x4) {
  if (blockIdx.x < DQ_BLOCKS) {
    __shared__ float cb[16];
    if (threadIdx.x < 16) cb[threadIdx.x] = c_nf4[threadIdx.x];
    __syncthreads();
    int t = blockIdx.x * 256 + threadIdx.x;
    int4 e = codes[t];
    float s = scale[t >> 9];
    uint4 o;
    __half2 h;
    h = __floats2half2_rn(cb[e.x & 15] * s, cb[(e.x >> 4) & 15] * s);
    o.x = reinterpret_cast<uint32_t&>(h);
    h = __floats2half2_rn(cb[e.y & 15] * s, cb[(e.y >> 4) & 15] * s);
    o.y = reinterpret_cast<uint32_t&>(h);
    h = __floats2half2_rn(cb[e.z & 15] * s, cb[(e.z >> 4) & 15] * s);
    o.z = reinterpret_cast<uint32_t&>(h);
    h = __floats2half2_rn(cb[e.w & 15] * s, cb[(e.w >> 4) & 15] * s);
    o.w = reinterpret_cast<uint32_t&>(h);
    reinterpret_cast<uint4*>(g_Wh)[t] = o;
  } else {
    int t = (blockIdx.x - DQ_BLOCKS) * 256 + threadIdx.x;
    float4 v0 = x4[2 * t];
    float4 v1 = x4[2 * t + 1];
    uint4 u;
    __half2 h;
    h = __floats2half2_rn(v0.x, v0.y);
    u.x = reinterpret_cast<uint32_t&>(h);
    h = __floats2half2_rn(v0.z, v0.w);
    u.y = reinterpret_cast<uint32_t&>(h);
    h = __floats2half2_rn(v1.x, v1.y);
    u.z = reinterpret_cast<uint32_t&>(h);
    h = __floats2half2_rn(v1.z, v1.w);
    u.w = reinterpret_cast<uint32_t&>(h);
    reinterpret_cast<uint4*>(g_Xh)[t] = u;
  }
}

// ------------------------------- GEMM kernel -------------------------------
// 128 threads = 4 warps in 2(m) x 2(n). Warp tile 64x64. 2 CTAs/SM.

__global__ __launch_bounds__(128, 2) void k_gemm(const float* __restrict__ bias,
                                                 float* __restrict__ out) {
  extern __shared__ char smem[];
  const uint32_t sb = smem_u32(smem);
  const int tid = threadIdx.x;
  const int wid = tid >> 5;
  const int lid = tid & 31;
  const int wm = wid & 1;
  const int wn = wid >> 1;
  const int n0 = blockIdx.x * BN;
  const int m0 = blockIdx.y * BM;

  if (tid == 0) {
#pragma unroll
    for (int s = 0; s < STAGES; ++s) {
      MBARRIER_INIT(sb + 8 * s, 128);       // full[s]
      MBARRIER_INIT(sb + 24 + 8 * s, 128);  // empty[s]
    }
  }
  __syncthreads();

  float c[4][8][4];
#pragma unroll
  for (int i = 0; i < 4; ++i)
#pragma unroll
    for (int j = 0; j < 8; ++j)
#pragma unroll
      for (int v = 0; v < 4; ++v) c[i][j][v] = 0.f;

  const int f_row = tid >> 3;  // 0..15
  const int f_u = tid & 7;
  const uint32_t f_sw_base = (uint32_t)(f_row * 128 + f_u * 16);
  const __half* aSrc0 = g_Xh + ((size_t)(m0 + f_row) * K_TOTAL + f_u * 8);
  const __half* bSrc0 = g_Wh + ((size_t)(n0 + f_row) * K_TOTAL + f_u * 8);

  // issue 2 A-chunks + 2 B-chunks (part 0..3) of stage s for k-iter ktp
  auto fill_part = [&](int s, int ktp, int part) {
    const uint32_t stage = sb + SM_STAGE0 + s * STAGE_BYTES;
    const size_t kOff = (size_t)ktp * BK;
#pragma unroll
    for (int j = 0; j < 2; ++j) {
      const int i = part * 2 + j;  // 0..7
      CP_ASYNC16(stage + SWZ128(f_sw_base + (uint32_t)(i * 16 * 128)),
                 (const void*)(aSrc0 + kOff + (size_t)16 * i * K_TOTAL));
    }
#pragma unroll
    for (int j = 0; j < 2; ++j) {
      const int i = part * 2 + j;
      CP_ASYNC16(stage + A_BYTES +
                     SWZ128(f_sw_base + (uint32_t)(i * 16 * 128)),
                 (const void*)(bSrc0 + kOff + (size_t)16 * i * K_TOTAL));
    }
  };

  // prologue: fill stages 0,1
#pragma unroll
  for (int p = 0; p < 4; ++p) fill_part(0, 0, p);
  CP_ASYNC_MBAR_ARRIVE(sb + 8 * 0);
#pragma unroll
  for (int p = 0; p < 4; ++p) fill_part(1, 1, p);
  CP_ASYNC_MBAR_ARRIVE(sb + 8 * 1);

  const int a_row = wm * 64 + (lid & 15);
  const int a_kb = (lid >> 4) * 16;
  const int b_row = wn * 64 + ((lid >> 4) * 8) + (lid & 7);
  const int b_kb = ((lid >> 3) & 1) * 16;

  int sp = 2, pp = 1;    // produce stage/parity
  int sc = 0, cpar = 0;  // consume stage/parity
  uint32_t pF = 0;       // probe-ahead result for full[sc]

  for (int kt = 0; kt < KITERS; ++kt) {
    const bool produce = (kt + 2 < KITERS);
    // next consume cursor (for the probe)
    const int nsc = (sc == 2) ? 0 : sc + 1;
    const int ncp = (nsc == 0) ? (cpar ^ 1) : cpar;

    if (!pF) MBARRIER_WAIT_PARITY(sb + 8 * sc, cpar);
    pF = 0;
    const uint32_t aBase = sb + SM_STAGE0 + sc * STAGE_BYTES;
    const uint32_t bBase = aBase + A_BYTES;

    // ---- ks = 0..2: split-wave consume; producer work at ks 1,2 ----
#pragma unroll
    for (int ks = 0; ks < 3; ++ks) {
      uint32_t a[4][4], b[4][4];
#pragma unroll
      for (int mt = 0; mt < 2; ++mt) {
        uint32_t off = (uint32_t)((a_row + mt * 16) * 128 + ks * 32 + a_kb);
        LDSM_X4(a[mt][0], a[mt][1], a[mt][2], a[mt][3], aBase + SWZ128(off));
      }
#pragma unroll
      for (int p = 0; p < 2; ++p) {
        uint32_t off = (uint32_t)((b_row + p * 16) * 128 + ks * 32 + b_kb);
        LDSM_X4(b[p][0], b[p][1], b[p][2], b[p][3], bBase + SWZ128(off));
      }
#pragma unroll
      for (int mt = 0; mt < 2; ++mt)
#pragma unroll
        for (int nt = 0; nt < 4; ++nt)
          MMA16816(c[mt][nt][0], c[mt][nt][1], c[mt][nt][2], c[mt][nt][3],
                   a[mt][0], a[mt][1], a[mt][2], a[mt][3],
                   b[nt >> 1][(nt & 1) * 2], b[nt >> 1][(nt & 1) * 2 + 1]);
#pragma unroll
      for (int mt = 2; mt < 4; ++mt) {
        uint32_t off = (uint32_t)((a_row + mt * 16) * 128 + ks * 32 + a_kb);
        LDSM_X4(a[mt][0], a[mt][1], a[mt][2], a[mt][3], aBase + SWZ128(off));
      }
#pragma unroll
      for (int p = 2; p < 4; ++p) {
        uint32_t off = (uint32_t)((b_row + p * 16) * 128 + ks * 32 + b_kb);
        LDSM_X4(b[p][0], b[p][1], b[p][2], b[p][3], bBase + SWZ128(off));
      }
      if (produce) {
        if (ks == 1) {
          MBARRIER_WAIT_PARITY_RELAXED(sb + 24 + 8 * sp, pp);
          fill_part(sp, kt + 2, 0);
          fill_part(sp, kt + 2, 1);
        } else if (ks == 2) {
          fill_part(sp, kt + 2, 2);
        }
      }
      if (ks == 2) {
        // probe next iteration's full barrier; latency hides under MMAs
        MBARRIER_PROBE(pF, sb + 8 * nsc, ncp);
      }
#pragma unroll
      for (int mt = 0; mt < 2; ++mt)
#pragma unroll
        for (int nt = 4; nt < 8; ++nt)
          MMA16816(c[mt][nt][0], c[mt][nt][1], c[mt][nt][2], c[mt][nt][3],
                   a[mt][0], a[mt][1], a[mt][2], a[mt][3],
                   b[nt >> 1][(nt & 1) * 2], b[nt >> 1][(nt & 1) * 2 + 1]);
#pragma unroll
      for (int mt = 2; mt < 4; ++mt)
#pragma unroll
        for (int nt = 0; nt < 8; ++nt)
          MMA16816(c[mt][nt][0], c[mt][nt][1], c[mt][nt][2], c[mt][nt][3],
                   a[mt][0], a[mt][1], a[mt][2], a[mt][3],
                   b[nt >> 1][(nt & 1) * 2], b[nt >> 1][(nt & 1) * 2 + 1]);
    }

    // ---- ks = 3: all LDSM first -> early release -> fill tail -> MMAs ----
    {
      const int ks = 3;
      uint32_t a[4][4], b[4][4];
#pragma unroll
      for (int mt = 0; mt < 4; ++mt) {
        uint32_t off = (uint32_t)((a_row + mt * 16) * 128 + ks * 32 + a_kb);
        LDSM_X4(a[mt][0], a[mt][1], a[mt][2], a[mt][3], aBase + SWZ128(off));
      }
#pragma unroll
      for (int p = 0; p < 4; ++p) {
        uint32_t off = (uint32_t)((b_row + p * 16) * 128 + ks * 32 + b_kb);
        LDSM_X4(b[p][0], b[p][1], b[p][2], b[p][3], bBase + SWZ128(off));
      }
      MBARRIER_ARRIVE(sb + 24 + 8 * sc);  // release stage ASAP
      if (produce) {
        fill_part(sp, kt + 2, 3);
        CP_ASYNC_MBAR_ARRIVE(sb + 8 * sp);  // seal produced stage
      }
#pragma unroll
      for (int mt = 0; mt < 4; ++mt)
#pragma unroll
        for (int nt = 0; nt < 8; ++nt)
          MMA16816(c[mt][nt][0], c[mt][nt][1], c[mt][nt][2], c[mt][nt][3],
                   a[mt][0], a[mt][1], a[mt][2], a[mt][3],
                   b[nt >> 1][(nt & 1) * 2], b[nt >> 1][(nt & 1) * 2 + 1]);
    }

    sp = (sp == 2) ? 0 : sp + 1;
    if (sp == 0) pp ^= 1;
    sc = nsc;
    cpar = ncp;
  }

  // ------------------------------ epilogue ---------------------------------
  const int mrow = m0 + wm * 64 + (lid >> 2);
  const int ncol = n0 + wn * 64 + (lid & 3) * 2;
  float2 bias2[8];
#pragma unroll
  for (int nt = 0; nt < 8; ++nt)
    bias2[nt] = *reinterpret_cast<const float2*>(bias + ncol + nt * 8);

#pragma unroll
  for (int mt = 0; mt < 4; ++mt) {
#pragma unroll
    for (int nt = 0; nt < 8; ++nt) {
      float* p0 = out + (size_t)(mrow + mt * 16) * N_TOTAL + ncol + nt * 8;
      float* p1 = p0 + 8 * N_TOTAL;
      float2 v0 = {c[mt][nt][0] + bias2[nt].x, c[mt][nt][1] + bias2[nt].y};
      float2 v1 = {c[mt][nt][2] + bias2[nt].x, c[mt][nt][3] + bias2[nt].y};
      *reinterpret_cast<float2*>(p0) = v0;
      *reinterpret_cast<float2*>(p1) = v1;
    }
  }
}

// ------------------------------- launcher ----------------------------------

extern "C" void kernel_launch(void* const* d_in, const int* in_sizes, int n_in,
                              void* d_out, int out_size) {
  const float* x = (const float*)d_in[0];
  const int* codes = (const int*)d_in[1];
  const float* scale = (const float*)d_in[2];
  const float* bias = (const float*)d_in[3];
  float* out = (float*)d_out;

  k_prep<<<DQ_BLOCKS + CV_BLOCKS, 256>>>((const int4*)codes, scale,
                                         (const float4*)x);

  cudaFuncSetAttribute(k_gemm, cudaFuncAttributeMaxDynamicSharedMemorySize,
                       SMEM_BYTES);
  dim3 grid(N_TOTAL / BN, M_TOTAL / BM);  // (32, 64)
  k_gemm<<<grid, 128, SMEM_BYTES>>>(bias, out);
}